// round 12
// baseline (speedup 1.0000x reference)
#include <cuda_runtime.h>
#include <cuda_fp16.h>

// bilateral_grid: [N=2, C=12, D=8, Hg=16, Wg=16] f32  (d_in[0])
// guidemap:       [N=2, 1, 2048, 2048] f32            (d_in[1])
// out:            [N=2, C=12, 2048, 2048] f32
//
// Champion structure + z-interleaved PAIR smem layout:
//   word[y*112 + zp*12 + 2*c2 + dz] = half2(ch 2*c2, 2*c2+1) at (y, z=zp+dz)
// One LDS.128 = {c01@z0, c01@z1, c23@z0, c23@z1} -> 6 LDS.128 per pixel
// (3 per y-row), each consumed immediately (no wide live structs).
// Bank groups (addr/4 mod 8): 4y + 3*z0; z0 in {3..6} -> {1,4,7,2},
// y+1 -> {5,0,3,6}: all 8 live rows distinct, 1 phase per load.

#define CG   12
#define DG   8
#define HGG  16
#define WGG  16
#define HH   2048
#define WW   2048

#define C2    6
#define ZPSTR 12            // words per z-pair row (6 channel-pairs x 2 z)
#define YSTR  112           // 7 pairs * 12 = 84 + 28 pad
#define SMEM_U32 (HGG * YSTR)

#define SCALE (15.0f / 2047.0f)

// Forced 16-byte shared load.
__device__ __forceinline__ uint4 lds128(const unsigned int* p)
{
    uint4 r;
    unsigned a = (unsigned)__cvta_generic_to_shared(p);
    asm("ld.shared.v4.u32 {%0,%1,%2,%3},[%4];"
        : "=r"(r.x), "=r"(r.y), "=r"(r.z), "=r"(r.w) : "r"(a));
    return r;
}

__device__ __forceinline__ __half2 as_h2(unsigned int u)
{
    return *reinterpret_cast<const __half2*>(&u);
}

// Fused 8-corner trilinear (y,z part) for one pixel -> 6 half2 channel pairs.
__device__ __forceinline__ void sample_half(const unsigned int* sg, int w, float g,
                                            __half2* s)
{
    const float iy = w * SCALE;                 // in [0, 15)
    const float iz = fmaf(g, 3.5f, 3.5f);       // in [3.5, 7]

    const int y0 = min((int)iy, HGG - 2);
    const int z0 = min((int)iz, DG - 2);        // pair index, in {3..6}
    const float fy = iy - (float)y0;
    const float fz = iz - (float)z0;

    const float wy1 = fy, wy0 = 1.0f - fy;
    const float wz1 = fz, wz0 = 1.0f - fz;

    const __half2 w00 = __float2half2_rn(wy0 * wz0);   // (y0, z0)
    const __half2 w10 = __float2half2_rn(wy0 * wz1);   // (y0, z1)
    const __half2 w01 = __float2half2_rn(wy1 * wz0);   // (y1, z0)
    const __half2 w11 = __float2half2_rn(wy1 * wz1);   // (y1, z1)

    const int base = y0 * YSTR + z0 * ZPSTR;

#pragma unroll
    for (int q = 0; q < 3; q++) {               // channel-pair quads
        const uint4 qa = lds128(sg + base + 4 * q);          // y0 row
        const uint4 qb = lds128(sg + base + YSTR + 4 * q);   // y1 row
        __half2 acc0 = __hmul2(w00, as_h2(qa.x));
        acc0 = __hfma2(w10, as_h2(qa.y), acc0);
        acc0 = __hfma2(w01, as_h2(qb.x), acc0);
        acc0 = __hfma2(w11, as_h2(qb.y), acc0);
        __half2 acc1 = __hmul2(w00, as_h2(qa.z));
        acc1 = __hfma2(w10, as_h2(qa.w), acc1);
        acc1 = __hfma2(w01, as_h2(qb.z), acc1);
        acc1 = __hfma2(w11, as_h2(qb.w), acc1);
        s[2 * q]     = acc0;
        s[2 * q + 1] = acc1;
    }
}

__global__ __launch_bounds__(256, 4)
void slice_kernel(const float* __restrict__ grid,
                  const float* __restrict__ guide,
                  float* __restrict__ out)
{
    __shared__ unsigned int sg[SMEM_U32];

    const int h = blockIdx.x;
    const int n = blockIdx.y;

    const float ix = h * SCALE;
    const int   x0 = min((int)ix, WGG - 2);
    const float fx = ix - (float)x0;
    const float wx1 = fx, wx0 = 1.0f - fx;

    const int HW = HH * WW;
    const float* gd   = guide + (size_t)n * HW + (size_t)h * WW;
    float*       outn = out   + (size_t)n * (CG * HW) + (size_t)h * WW;

    // Prefetch all 4 guide pairs (overlaps DRAM latency with smem staging).
    float2 gv[4];
#pragma unroll
    for (int it = 0; it < 4; it++)
        gv[it] = *reinterpret_cast<const float2*>(gd + it * 512 + threadIdx.x * 2);

    // ---- stage z-pair rows: one word per (y, zp, j), j = 2*c2 + dz ----
    const float* gsrc = grid + (size_t)n * (CG * DG * HGG * WGG);
    for (int i = threadIdx.x; i < HGG * 7 * ZPSTR; i += blockDim.x) {
        const int j  = i % ZPSTR;           // 0..11
        const int t  = i / ZPSTR;
        const int zp = t % 7;
        const int y  = t / 7;
        const int dz = j & 1;
        const int c2 = j >> 1;
        const int z  = zp + dz;
        const int c0 = 2 * c2, c1 = c0 + 1;
        const int b0 = ((c0 * DG + z) * HGG + y) * WGG + x0;
        const int b1 = ((c1 * DG + z) * HGG + y) * WGG + x0;
        const float v0 = wx0 * gsrc[b0] + wx1 * gsrc[b0 + 1];
        const float v1 = wx0 * gsrc[b1] + wx1 * gsrc[b1 + 1];
        const __half2 p = __floats2half2_rn(v0, v1);
        sg[y * YSTR + zp * ZPSTR + j] = *reinterpret_cast<const unsigned int*>(&p);
    }
    __syncthreads();

#pragma unroll
    for (int it = 0; it < 4; it++) {
        const int w0 = it * 512 + threadIdx.x * 2;

        __half2 s[C2], t[C2];
        sample_half(sg, w0,     gv[it].x, s);
        sample_half(sg, w0 + 1, gv[it].y, t);

#pragma unroll
        for (int k = 0; k < C2; k++) {
            const float2 a = __half22float2(s[k]);
            const float2 b = __half22float2(t[k]);
            const float2 o0 = make_float2(a.x, b.x);   // channel 2k
            const float2 o1 = make_float2(a.y, b.y);   // channel 2k+1
            *reinterpret_cast<float2*>(outn + (size_t)(2 * k)     * HW + w0) = o0;
            *reinterpret_cast<float2*>(outn + (size_t)(2 * k + 1) * HW + w0) = o1;
        }
    }
}

extern "C" void kernel_launch(void* const* d_in, const int* in_sizes, int n_in,
                              void* d_out, int out_size)
{
    const float* grid  = (const float*)d_in[0];
    const float* guide = (const float*)d_in[1];
    float*       out   = (float*)d_out;

    dim3 gdim(HH, 2);            // one block per (row, batch)
    slice_kernel<<<gdim, 256>>>(grid, guide, out);
}

// round 13
// speedup vs baseline: 1.0322x; 1.0322x over previous
#include <cuda_runtime.h>
#include <cuda_fp16.h>

// bilateral_grid: [N=2, C=12, D=8, Hg=16, Wg=16] f32  (d_in[0])
// guidemap:       [N=2, 1, 2048, 2048] f32            (d_in[1])
// out:            [N=2, C=12, 2048, 2048] f32
//
// Champion (R7/R11) structure with half-row scheduling grain:
// one block per (n, h, half): x-interp hoisted per row -> Gx[y][z][c-pair]
// (half2) in smem, conflict-free LDS.64 layout (offset/2 mod 16 distinct
// across all 10 warp-live corner rows). Each thread: 2 consecutive pixels
// x 2 iterations; guide prefetched before the staging barrier; plain STG.64.

#define CG   12
#define DG   8
#define HGG  16
#define WGG  16
#define HH   2048
#define WW   2048

#define C2    6
#define ZSTR  6
#define YSTR  98
#define SMEM_U32 (HGG * YSTR + 8)

#define SCALE (15.0f / 2047.0f)

// Forced 8-byte shared load (prevents ptxas fusing into wide LDS).
__device__ __forceinline__ uint2 lds64(const unsigned int* p)
{
    uint2 r;
    unsigned a = (unsigned)__cvta_generic_to_shared(p);
    asm("ld.shared.v2.u32 {%0,%1},[%2];" : "=r"(r.x), "=r"(r.y) : "r"(a));
    return r;
}

struct Row6 { __half2 v[C2]; };

__device__ __forceinline__ Row6 load_row(const unsigned int* sg, int off)
{
    Row6 r;
    const uint2 a = lds64(sg + off);
    const uint2 b = lds64(sg + off + 2);
    const uint2 c = lds64(sg + off + 4);
    r.v[0] = *reinterpret_cast<const __half2*>(&a.x);
    r.v[1] = *reinterpret_cast<const __half2*>(&a.y);
    r.v[2] = *reinterpret_cast<const __half2*>(&b.x);
    r.v[3] = *reinterpret_cast<const __half2*>(&b.y);
    r.v[4] = *reinterpret_cast<const __half2*>(&c.x);
    r.v[5] = *reinterpret_cast<const __half2*>(&c.y);
    return r;
}

// Fused 4-corner (y,z) weighted sum for one pixel -> 6 half2 channel pairs.
__device__ __forceinline__ void sample_half(const unsigned int* sg, int w, float g,
                                            __half2* s)
{
    const float iy = w * SCALE;                 // in [0, 15)
    const float iz = fmaf(g, 3.5f, 3.5f);       // in [3.5, 7]

    const int y0 = min((int)iy, HGG - 2);
    const int z0 = min((int)iz, DG - 2);
    const float fy = iy - (float)y0;
    const float fz = iz - (float)z0;

    const float wy1 = fy, wy0 = 1.0f - fy;
    const float wz1 = fz, wz0 = 1.0f - fz;

    const __half2 w00 = __float2half2_rn(wy0 * wz0);
    const __half2 w01 = __float2half2_rn(wy1 * wz0);
    const __half2 w10 = __float2half2_rn(wy0 * wz1);
    const __half2 w11 = __float2half2_rn(wy1 * wz1);

    const int a00 = y0 * YSTR + z0 * ZSTR;
    const Row6 A  = load_row(sg, a00);                 // (y0, z0)
    const Row6 B  = load_row(sg, a00 + YSTR);          // (y1, z0)
    const Row6 Cc = load_row(sg, a00 + ZSTR);          // (y0, z1)
    const Row6 Dd = load_row(sg, a00 + YSTR + ZSTR);   // (y1, z1)

#pragma unroll
    for (int k = 0; k < C2; k++) {
        __half2 acc = __hmul2(w00, A.v[k]);
        acc = __hfma2(w01, B.v[k],  acc);
        acc = __hfma2(w10, Cc.v[k], acc);
        acc = __hfma2(w11, Dd.v[k], acc);
        s[k] = acc;
    }
}

__global__ __launch_bounds__(256, 4)
void slice_kernel(const float* __restrict__ grid,
                  const float* __restrict__ guide,
                  float* __restrict__ out)
{
    __shared__ unsigned int sg[SMEM_U32];

    const int h    = blockIdx.x >> 1;          // row
    const int woff = (blockIdx.x & 1) << 10;   // half-row offset (0 or 1024)
    const int n    = blockIdx.y;

    const float ix = h * SCALE;
    const int   x0 = min((int)ix, WGG - 2);
    const float fx = ix - (float)x0;
    const float wx1 = fx, wx0 = 1.0f - fx;

    const int HW = HH * WW;
    const float* gd   = guide + (size_t)n * HW + (size_t)h * WW + woff;
    float*       outn = out   + (size_t)n * (CG * HW) + (size_t)h * WW + woff;

    // Prefetch both guide pairs (overlaps DRAM latency with smem staging).
    float2 gv[2];
#pragma unroll
    for (int it = 0; it < 2; it++)
        gv[it] = *reinterpret_cast<const float2*>(gd + it * 512 + threadIdx.x * 2);

    // ---- stage Gx as half2 channel pairs: sg[y*YSTR + z*ZSTR + c2] ----
    const float* gsrc = grid + (size_t)n * (CG * DG * HGG * WGG);
    for (int i = threadIdx.x; i < DG * HGG * C2; i += blockDim.x) {
        const int c2 = i % C2;
        const int t  = i / C2;
        const int y  = t % HGG;
        const int z  = t / HGG;
        const int c0 = 2 * c2, c1 = c0 + 1;
        const int b0 = ((c0 * DG + z) * HGG + y) * WGG + x0;
        const int b1 = ((c1 * DG + z) * HGG + y) * WGG + x0;
        const float v0 = wx0 * gsrc[b0] + wx1 * gsrc[b0 + 1];
        const float v1 = wx0 * gsrc[b1] + wx1 * gsrc[b1 + 1];
        const __half2 p = __floats2half2_rn(v0, v1);
        sg[y * YSTR + z * ZSTR + c2] = *reinterpret_cast<const unsigned int*>(&p);
    }
    __syncthreads();

#pragma unroll
    for (int it = 0; it < 2; it++) {
        const int w0   = it * 512 + threadIdx.x * 2;   // within half-row
        const int wloc = woff + w0;                    // within full row

        __half2 s[C2], t[C2];
        sample_half(sg, wloc,     gv[it].x, s);
        sample_half(sg, wloc + 1, gv[it].y, t);

#pragma unroll
        for (int k = 0; k < C2; k++) {
            const float2 a = __half22float2(s[k]);
            const float2 b = __half22float2(t[k]);
            const float2 o0 = make_float2(a.x, b.x);   // channel 2k
            const float2 o1 = make_float2(a.y, b.y);   // channel 2k+1
            *reinterpret_cast<float2*>(outn + (size_t)(2 * k)     * HW + w0) = o0;
            *reinterpret_cast<float2*>(outn + (size_t)(2 * k + 1) * HW + w0) = o1;
        }
    }
}

extern "C" void kernel_launch(void* const* d_in, const int* in_sizes, int n_in,
                              void* d_out, int out_size)
{
    const float* grid  = (const float*)d_in[0];
    const float* guide = (const float*)d_in[1];
    float*       out   = (float*)d_out;

    dim3 gdim(HH * 2, 2);        // one block per (half-row, batch)
    slice_kernel<<<gdim, 256>>>(grid, guide, out);
}

// round 14
// speedup vs baseline: 1.2839x; 1.2438x over previous
#include <cuda_runtime.h>
#include <cuda_fp16.h>

// bilateral_grid: [N=2, C=12, D=8, Hg=16, Wg=16] f32  (d_in[0])
// guidemap:       [N=2, 1, 2048, 2048] f32            (d_in[1])
// out:            [N=2, C=12, 2048, 2048] f32
//
// Champion configuration (R7/R11, 77.9us): one block per (n, h) row; x-interp
// hoisted per row -> Gx[y][z][c-pair] (half2) in smem. Layout is conflict-free
// for LDS.64:
//   word offset = y*98 + z*6 + c2; bank-pair group = offset/2 mod 16
//   z=3..7 (y0): {9,12,15,2,5}; y1 adds 49 mod 16 = 1 -> {10,13,0,3,6}
//   -> all 10 warp-live corner rows in distinct bank pairs, 1 phase each.
// Each thread: 2 consecutive pixels x 4 iterations (512-px stride);
// guide prefetched before the staging barrier; plain STG.64 stores.
// Measured falsifications (do not revisit): LDS.128/packed rows (R9,R12),
// STG.128 4px/thread (R4,R8), occ=5 (R6), __stcs (R10), half-row grain
// (R10,R13) -- all regress or are neutral vs this configuration.

#define CG   12
#define DG   8
#define HGG  16
#define WGG  16
#define HH   2048
#define WW   2048

#define C2    6
#define ZSTR  6
#define YSTR  98
#define SMEM_U32 (HGG * YSTR + 8)

#define SCALE (15.0f / 2047.0f)

// Forced 8-byte shared load (prevents ptxas fusing into conflicted LDS.128).
__device__ __forceinline__ uint2 lds64(const unsigned int* p)
{
    uint2 r;
    unsigned a = (unsigned)__cvta_generic_to_shared(p);
    asm("ld.shared.v2.u32 {%0,%1},[%2];" : "=r"(r.x), "=r"(r.y) : "r"(a));
    return r;
}

struct Row6 { __half2 v[C2]; };

__device__ __forceinline__ Row6 load_row(const unsigned int* sg, int off)
{
    Row6 r;
    const uint2 a = lds64(sg + off);
    const uint2 b = lds64(sg + off + 2);
    const uint2 c = lds64(sg + off + 4);
    r.v[0] = *reinterpret_cast<const __half2*>(&a.x);
    r.v[1] = *reinterpret_cast<const __half2*>(&a.y);
    r.v[2] = *reinterpret_cast<const __half2*>(&b.x);
    r.v[3] = *reinterpret_cast<const __half2*>(&b.y);
    r.v[4] = *reinterpret_cast<const __half2*>(&c.x);
    r.v[5] = *reinterpret_cast<const __half2*>(&c.y);
    return r;
}

// Fused 4-corner (y,z) weighted sum for one pixel -> 6 half2 channel pairs.
__device__ __forceinline__ void sample_half(const unsigned int* sg, int w, float g,
                                            __half2* s)
{
    const float iy = w * SCALE;                 // in [0, 15)
    const float iz = fmaf(g, 3.5f, 3.5f);       // in [3.5, 7]

    const int y0 = min((int)iy, HGG - 2);
    const int z0 = min((int)iz, DG - 2);
    const float fy = iy - (float)y0;
    const float fz = iz - (float)z0;

    const float wy1 = fy, wy0 = 1.0f - fy;
    const float wz1 = fz, wz0 = 1.0f - fz;

    const __half2 w00 = __float2half2_rn(wy0 * wz0);
    const __half2 w01 = __float2half2_rn(wy1 * wz0);
    const __half2 w10 = __float2half2_rn(wy0 * wz1);
    const __half2 w11 = __float2half2_rn(wy1 * wz1);

    const int a00 = y0 * YSTR + z0 * ZSTR;
    const Row6 A  = load_row(sg, a00);                 // (y0, z0)
    const Row6 B  = load_row(sg, a00 + YSTR);          // (y1, z0)
    const Row6 Cc = load_row(sg, a00 + ZSTR);          // (y0, z1)
    const Row6 Dd = load_row(sg, a00 + YSTR + ZSTR);   // (y1, z1)

#pragma unroll
    for (int k = 0; k < C2; k++) {
        __half2 acc = __hmul2(w00, A.v[k]);
        acc = __hfma2(w01, B.v[k],  acc);
        acc = __hfma2(w10, Cc.v[k], acc);
        acc = __hfma2(w11, Dd.v[k], acc);
        s[k] = acc;
    }
}

__global__ __launch_bounds__(256, 4)
void slice_kernel(const float* __restrict__ grid,
                  const float* __restrict__ guide,
                  float* __restrict__ out)
{
    __shared__ unsigned int sg[SMEM_U32];

    const int h = blockIdx.x;
    const int n = blockIdx.y;

    const float ix = h * SCALE;
    const int   x0 = min((int)ix, WGG - 2);
    const float fx = ix - (float)x0;
    const float wx1 = fx, wx0 = 1.0f - fx;

    const int HW = HH * WW;
    const float* gd   = guide + (size_t)n * HW + (size_t)h * WW;
    float*       outn = out   + (size_t)n * (CG * HW) + (size_t)h * WW;

    // Prefetch all 4 guide pairs (overlaps DRAM latency with smem staging).
    float2 gv[4];
#pragma unroll
    for (int it = 0; it < 4; it++)
        gv[it] = *reinterpret_cast<const float2*>(gd + it * 512 + threadIdx.x * 2);

    // ---- stage Gx as half2 channel pairs: sg[y*YSTR + z*ZSTR + c2] ----
    const float* gsrc = grid + (size_t)n * (CG * DG * HGG * WGG);
    for (int i = threadIdx.x; i < DG * HGG * C2; i += blockDim.x) {
        const int c2 = i % C2;
        const int t  = i / C2;
        const int y  = t % HGG;
        const int z  = t / HGG;
        const int c0 = 2 * c2, c1 = c0 + 1;
        const int b0 = ((c0 * DG + z) * HGG + y) * WGG;
        const int b1 = ((c1 * DG + z) * HGG + y) * WGG;
        const float v0 = wx0 * gsrc[b0 + x0] + wx1 * gsrc[b0 + x0 + 1];
        const float v1 = wx0 * gsrc[b1 + x0] + wx1 * gsrc[b1 + x0 + 1];
        const __half2 p = __floats2half2_rn(v0, v1);
        sg[y * YSTR + z * ZSTR + c2] = *reinterpret_cast<const unsigned int*>(&p);
    }
    __syncthreads();

#pragma unroll
    for (int it = 0; it < 4; it++) {
        const int w0 = it * 512 + threadIdx.x * 2;

        __half2 s[C2], t[C2];
        sample_half(sg, w0,     gv[it].x, s);
        sample_half(sg, w0 + 1, gv[it].y, t);

#pragma unroll
        for (int k = 0; k < C2; k++) {
            const float2 a = __half22float2(s[k]);
            const float2 b = __half22float2(t[k]);
            const float2 o0 = make_float2(a.x, b.x);   // channel 2k
            const float2 o1 = make_float2(a.y, b.y);   // channel 2k+1
            *reinterpret_cast<float2*>(outn + (size_t)(2 * k)     * HW + w0) = o0;
            *reinterpret_cast<float2*>(outn + (size_t)(2 * k + 1) * HW + w0) = o1;
        }
    }
}

extern "C" void kernel_launch(void* const* d_in, const int* in_sizes, int n_in,
                              void* d_out, int out_size)
{
    const float* grid  = (const float*)d_in[0];
    const float* guide = (const float*)d_in[1];
    float*       out   = (float*)d_out;

    dim3 gdim(HH, 2);            // one block per (row, batch)
    slice_kernel<<<gdim, 256>>>(grid, guide, out);
}